// round 1
// baseline (speedup 1.0000x reference)
#include <cuda_runtime.h>
#include <cuda_bf16.h>

// Problem constants (fixed by setup_inputs)
#define BS 2
#define LQ 384
#define LK 384
#define NH 8
#define DQ 32
#define DK 32
#define DV 32
#define DC 64
#define BH (BS*NH)          // 16
#define QTILE 16            // q rows per block (one per warp)
#define NKT (LK/32)         // 12 k-tiles per warp

// Scratch (allocation-free rule: __device__ globals)
__device__ float g_qW[BH * LQ * DC];        // [bh][q][e]
__device__ float g_kWT[BH * DC * LK];       // [bh][e][k]  (includes b1)

// ---------------------------------------------------------------------------
// Pre-kernel: qW = q @ W1[:DQ]   (layout [bh][q][e], e-coalesced stores)
//             kWbT = (k @ W1[DQ:]) + b1, transposed to [bh][e][k]
// grid (12, 16, 2) block 256
// ---------------------------------------------------------------------------
__global__ void __launch_bounds__(256) pre_kernel(
    const float* __restrict__ qin, const float* __restrict__ kin,
    const float* __restrict__ w1, const float* __restrict__ b1)
{
    __shared__ float w1s[32 * 64];       // [d][e] half of W1 for this head
    __shared__ float rows_s[32 * 33];    // 32 input rows x 32 dims, padded

    const int bh   = blockIdx.y;
    const int b    = bh >> 3;
    const int h    = bh & 7;
    const int row0 = blockIdx.x * 32;
    const int side = blockIdx.z;         // 0 = q-side, 1 = k-side
    const int tid  = threadIdx.x;

    const float* in = side ? kin : qin;
    const int woff = h * (DC * DC) + side * (DQ * DC);  // w1[h][side*32 + d][e]

    for (int i = tid; i < 32 * 64; i += 256) w1s[i] = w1[woff + i];
    {
        const int r = tid >> 5, d = tid & 31;
        #pragma unroll
        for (int p = 0; p < 4; p++) {
            const int rr = p * 8 + r;
            rows_s[rr * 33 + d] = in[(b * LQ + row0 + rr) * (NH * 32) + h * 32 + d];
        }
    }
    __syncthreads();

    if (side == 0) {
        // lanes over e (coalesced [q][e] stores)
        const int el = tid & 63;         // e
        const int rg = tid >> 6;         // 0..3
        #pragma unroll
        for (int i = 0; i < 8; i++) {
            const int r = rg * 8 + i;
            float acc = 0.f;
            #pragma unroll
            for (int d = 0; d < 32; d++)
                acc = fmaf(rows_s[r * 33 + d], w1s[d * 64 + el], acc);
            g_qW[(bh * LQ + row0 + r) * DC + el] = acc;
        }
    } else {
        // lanes over k (coalesced [e][k] stores)
        const int kl = tid & 31;         // k within tile
        const int eg = tid >> 5;         // 0..7
        float acc[8];
        #pragma unroll
        for (int j = 0; j < 8; j++) acc[j] = b1[h * DC + eg * 8 + j];
        #pragma unroll
        for (int d = 0; d < 32; d++) {
            const float rv = rows_s[kl * 33 + d];
            #pragma unroll
            for (int j = 0; j < 8; j++)
                acc[j] = fmaf(rv, w1s[d * 64 + eg * 8 + j], acc[j]);
        }
        #pragma unroll
        for (int j = 0; j < 8; j++)
            g_kWT[(bh * DC + eg * 8 + j) * LK + row0 + kl] = acc[j];
    }
}

// ---------------------------------------------------------------------------
// Main kernel: scores + softmax + att store + AV
// grid (LQ/QTILE=24, BH=16), block 512 (16 warps = 16 q rows)
// smem layout (floats):
//   kws   [64][384]   24576   (pre-scaled by 2*log2(e))
//   qws   [16][64]     1024   (pre-scaled)
//   w2s   [64]           64
//   w2sum [1]             1 (+7 pad)
//   probs [16][384]    6144
//   vs    [384][32]   12288
// ---------------------------------------------------------------------------
#define SM_KWS   0
#define SM_QWS   24576
#define SM_W2    25600
#define SM_W2SUM 25664
#define SM_PROBS 25672
#define SM_VS    31816
#define SM_FLOATS 44104
#define SMEM_BYTES (SM_FLOATS * 4)

__global__ void __launch_bounds__(512, 1) main_kernel(
    const float* __restrict__ v,
    const int* __restrict__ qlens, const int* __restrict__ klens,
    const float* __restrict__ w2g,
    float* __restrict__ outp, float* __restrict__ attp)
{
    extern __shared__ float sm[];
    float* kws   = sm + SM_KWS;
    float* qws   = sm + SM_QWS;
    float* w2s   = sm + SM_W2;
    float* w2sum_s = sm + SM_W2SUM;
    float* probs = sm + SM_PROBS;
    float* vs    = sm + SM_VS;

    const int tid  = threadIdx.x;
    const int w    = tid >> 5;
    const int lane = tid & 31;
    const int bh   = blockIdx.y;
    const int b    = bh >> 3;
    const int h    = bh & 7;
    const int q    = blockIdx.x * QTILE + w;

    const float L = 2.8853900817779268f;   // 2 * log2(e): tanh(x)=1-2/(exp2(L*x)+1)

    for (int i = tid; i < DC * LK; i += 512) kws[i] = g_kWT[bh * (DC * LK) + i] * L;
    for (int i = tid; i < QTILE * DC; i += 512) {
        const int qq = blockIdx.x * QTILE + (i >> 6);
        qws[i] = g_qW[(bh * LQ + qq) * DC + (i & 63)] * L;
    }
    if (tid < 64) w2s[tid] = w2g[h * DC + tid];
    for (int i = tid; i < LK * 32; i += 512)
        vs[i] = v[(b * LK + (i >> 5)) * (NH * 32) + h * 32 + (i & 31)];
    __syncthreads();
    if (tid == 0) {
        float s = 0.f;
        for (int e = 0; e < DC; e++) s += w2s[e];
        *w2sum_s = s;
    }
    __syncthreads();
    const float w2sum = *w2sum_s;

    float acc[NKT];
    #pragma unroll
    for (int t = 0; t < NKT; t++) acc[t] = 0.f;

    // score[k] = sum_e w2[e] * tanh(qW[e]+kWb[k][e])
    //          = w2sum - 2 * sum_e w2[e] / (exp2(L*(qW+kWb)) + 1)
    #pragma unroll 2
    for (int e = 0; e < DC; e++) {
        const float qe  = qws[w * DC + e];
        const float w2e = w2s[e];
        const float* kr = kws + e * LK + lane;
        #pragma unroll
        for (int t = 0; t < NKT; t++) {
            const float x = kr[t * 32] + qe;
            float ex; asm("ex2.approx.f32 %0, %1;" : "=f"(ex) : "f"(x));
            float r;  asm("rcp.approx.f32 %0, %1;" : "=f"(r)  : "f"(ex + 1.0f));
            acc[t] = fmaf(w2e, r, acc[t]);
        }
    }

    const int klen = klens[b];
    float m = -3.0e38f;
    float sc[NKT];
    #pragma unroll
    for (int t = 0; t < NKT; t++) {
        sc[t] = w2sum - 2.0f * acc[t];
        if (t * 32 + lane < klen) m = fmaxf(m, sc[t]);
    }
    #pragma unroll
    for (int o = 16; o > 0; o >>= 1) m = fmaxf(m, __shfl_xor_sync(0xffffffffu, m, o));

    float sum = 0.f;
    #pragma unroll
    for (int t = 0; t < NKT; t++) {
        const float p = (t * 32 + lane < klen) ? __expf(sc[t] - m) : 0.f;
        sc[t] = p;
        sum += p;
    }
    #pragma unroll
    for (int o = 16; o > 0; o >>= 1) sum += __shfl_xor_sync(0xffffffffu, sum, o);
    const float inv = 1.0f / sum;

    float* pr = probs + w * LK;
    const int attbase = (bh * LQ + q) * LK;
    #pragma unroll
    for (int t = 0; t < NKT; t++) {
        const float p = sc[t] * inv;
        pr[t * 32 + lane] = p;
        if (attp) attp[attbase + t * 32 + lane] = p;
    }
    __syncwarp();

    // AV: lanes switch role to d
    float o = 0.f;
    int kk = 0;
    for (; kk + 4 <= klen; kk += 4) {
        o = fmaf(pr[kk + 0], vs[(kk + 0) * 32 + lane], o);
        o = fmaf(pr[kk + 1], vs[(kk + 1) * 32 + lane], o);
        o = fmaf(pr[kk + 2], vs[(kk + 2) * 32 + lane], o);
        o = fmaf(pr[kk + 3], vs[(kk + 3) * 32 + lane], o);
    }
    for (; kk < klen; kk++) o = fmaf(pr[kk], vs[kk * 32 + lane], o);

    const int qlen = qlens[b];
    outp[((b * LQ + q) * NH + h) * 32 + lane] = (q < qlen) ? o : 0.f;
}

// ---------------------------------------------------------------------------
extern "C" void kernel_launch(void* const* d_in, const int* in_sizes, int n_in,
                              void* d_out, int out_size)
{
    const float* q    = (const float*)d_in[0];
    const float* k    = (const float*)d_in[1];
    const float* v    = (const float*)d_in[2];
    const int*   qlen = (const int*)  d_in[3];
    const int*   klen = (const int*)  d_in[4];
    const float* w1   = (const float*)d_in[5];
    const float* b1   = (const float*)d_in[6];
    const float* w2   = (const float*)d_in[7];

    float* outp = (float*)d_out;
    const int OUT_ELEMS = BS * LQ * NH * DV;          // 196608
    const int ATT_ELEMS = BH * LQ * LK;               // 2359296
    float* attp = (out_size >= OUT_ELEMS + ATT_ELEMS) ? (outp + OUT_ELEMS) : nullptr;

    pre_kernel<<<dim3(LQ / 32, BH, 2), 256>>>(q, k, w1, b1);

    cudaFuncSetAttribute(main_kernel, cudaFuncAttributeMaxDynamicSharedMemorySize, SMEM_BYTES);
    main_kernel<<<dim3(LQ / QTILE, BH), 512, SMEM_BYTES>>>(v, qlen, klen, w2, outp, attp);
}

// round 4
// speedup vs baseline: 1.6106x; 1.6106x over previous
#include <cuda_runtime.h>
#include <cuda_bf16.h>

// Problem constants (fixed by setup_inputs)
#define BS 2
#define LQ 384
#define LK 384
#define NH 8
#define DQ 32
#define DK 32
#define DV 32
#define DC 64
#define BH (BS*NH)          // 16
#define QTILE 16            // q rows per block (one per warp)
#define NG 3                // float4 groups of k per lane (3*4*32 = 384)

// Scratch (allocation-free rule: __device__ globals), 16B aligned for float4
__device__ __align__(16) float g_qW[BH * LQ * DC];        // [bh][q][e]
__device__ __align__(16) float g_kWT[BH * DC * LK];       // [bh][e][k]  (includes b1)

// ---------------------------------------------------------------------------
// Pre-kernel: qW = q @ W1[:DQ]   (layout [bh][q][e], e-coalesced stores)
//             kWbT = (k @ W1[DQ:]) + b1, transposed to [bh][e][k]
// grid (12, 16, 2) block 256
// ---------------------------------------------------------------------------
__global__ void __launch_bounds__(256) pre_kernel(
    const float* __restrict__ qin, const float* __restrict__ kin,
    const float* __restrict__ w1, const float* __restrict__ b1)
{
    __shared__ float w1s[32 * 64];       // [d][e] half of W1 for this head
    __shared__ float rows_s[32 * 33];    // 32 input rows x 32 dims, padded

    const int bh   = blockIdx.y;
    const int b    = bh >> 3;
    const int h    = bh & 7;
    const int row0 = blockIdx.x * 32;
    const int side = blockIdx.z;         // 0 = q-side, 1 = k-side
    const int tid  = threadIdx.x;

    const float* in = side ? kin : qin;
    const int woff = h * (DC * DC) + side * (DQ * DC);  // w1[h][side*32 + d][e]

    for (int i = tid; i < 32 * 64; i += 256) w1s[i] = w1[woff + i];
    {
        const int r = tid >> 5, d = tid & 31;
        #pragma unroll
        for (int p = 0; p < 4; p++) {
            const int rr = p * 8 + r;
            rows_s[rr * 33 + d] = in[(b * LQ + row0 + rr) * (NH * 32) + h * 32 + d];
        }
    }
    __syncthreads();

    if (side == 0) {
        // lanes over e (coalesced [q][e] stores)
        const int el = tid & 63;         // e
        const int rg = tid >> 6;         // 0..3
        #pragma unroll
        for (int i = 0; i < 8; i++) {
            const int r = rg * 8 + i;
            float acc = 0.f;
            #pragma unroll
            for (int d = 0; d < 32; d++)
                acc = fmaf(rows_s[r * 33 + d], w1s[d * 64 + el], acc);
            g_qW[(bh * LQ + row0 + r) * DC + el] = acc;
        }
    } else {
        // lanes over k (coalesced [e][k] stores)
        const int kl = tid & 31;         // k within tile
        const int eg = tid >> 5;         // 0..7
        float acc[8];
        #pragma unroll
        for (int j = 0; j < 8; j++) acc[j] = b1[h * DC + eg * 8 + j];
        #pragma unroll
        for (int d = 0; d < 32; d++) {
            const float rv = rows_s[kl * 33 + d];
            #pragma unroll
            for (int j = 0; j < 8; j++)
                acc[j] = fmaf(rv, w1s[d * 64 + eg * 8 + j], acc[j]);
        }
        #pragma unroll
        for (int j = 0; j < 8; j++)
            g_kWT[(bh * DC + eg * 8 + j) * LK + row0 + kl] = acc[j];
    }
}

// ---------------------------------------------------------------------------
// Main kernel: scores (tanh.approx) + softmax + att store + AV
// grid (LQ/QTILE=24, BH=16), block 512 (16 warps = 16 q rows)
// smem floats:
//   kws   [64][384]   24576
//   qws   [16][64]     1024
//   w2s   [64]           64  (+pad 8)
//   probs [16][384]    6144
//   vs    [384][32]   12288
// ---------------------------------------------------------------------------
#define SM_KWS   0
#define SM_QWS   24576
#define SM_W2    25600
#define SM_PROBS 25672
#define SM_VS    31816
#define SM_FLOATS 44104
#define SMEM_BYTES (SM_FLOATS * 4)

__global__ void __launch_bounds__(512, 1) main_kernel(
    const float* __restrict__ v,
    const int* __restrict__ qlens, const int* __restrict__ klens,
    const float* __restrict__ w2g,
    float* __restrict__ outp, float* __restrict__ attp)
{
    extern __shared__ float sm[];
    float* kws   = sm + SM_KWS;
    float* qws   = sm + SM_QWS;
    float* w2s   = sm + SM_W2;
    float* probs = sm + SM_PROBS;
    float* vs    = sm + SM_VS;

    const int tid  = threadIdx.x;
    const int w    = tid >> 5;
    const int lane = tid & 31;
    const int bh   = blockIdx.y;
    const int b    = bh >> 3;
    const int h    = bh & 7;
    const int q    = blockIdx.x * QTILE + w;

    // ---- load phase (vectorized) ----
    {
        const float4* src = (const float4*)(g_kWT + bh * (DC * LK));
        float4* dst = (float4*)kws;
        #pragma unroll
        for (int i = 0; i < (DC * LK / 4) / 512; i++)      // 12 iters
            dst[tid + i * 512] = src[tid + i * 512];
    }
    for (int i = tid; i < QTILE * DC; i += 512) {
        const int qq = blockIdx.x * QTILE + (i >> 6);
        qws[i] = g_qW[(bh * LQ + qq) * DC + (i & 63)];
    }
    if (tid < 64) w2s[tid] = w2g[h * DC + tid];
    {
        // vs[row][d], row-stride 32 floats; v row stride = NH*32 floats
        float4* dst = (float4*)vs;
        #pragma unroll
        for (int i = 0; i < (LK * 32 / 4) / 512; i++) {    // 6 iters
            const int idx = tid + i * 512;                 // float4 index
            const int row = idx >> 3, c4 = idx & 7;
            dst[idx] = ((const float4*)(v + (b * LK + row) * (NH * 32) + h * 32))[c4];
        }
    }
    __syncthreads();

    // ---- score phase: acc[g][j] = sum_e w2[e]*tanh(qW[e] + kWb[k][e])
    // lane owns k = g*128 + lane*4 + j
    float4 acc[NG];
    #pragma unroll
    for (int g = 0; g < NG; g++) acc[g] = make_float4(0.f, 0.f, 0.f, 0.f);

    #pragma unroll 2
    for (int e = 0; e < DC; e++) {
        const float qe  = qws[w * DC + e];
        const float w2e = w2s[e];
        const float4* kr = ((const float4*)(kws + e * LK)) + lane;
        #pragma unroll
        for (int g = 0; g < NG; g++) {
            const float4 kv = kr[g * 32];
            float t0, t1, t2, t3;
            asm("tanh.approx.f32 %0, %1;" : "=f"(t0) : "f"(kv.x + qe));
            asm("tanh.approx.f32 %0, %1;" : "=f"(t1) : "f"(kv.y + qe));
            asm("tanh.approx.f32 %0, %1;" : "=f"(t2) : "f"(kv.z + qe));
            asm("tanh.approx.f32 %0, %1;" : "=f"(t3) : "f"(kv.w + qe));
            acc[g].x = fmaf(w2e, t0, acc[g].x);
            acc[g].y = fmaf(w2e, t1, acc[g].y);
            acc[g].z = fmaf(w2e, t2, acc[g].z);
            acc[g].w = fmaf(w2e, t3, acc[g].w);
        }
    }

    // ---- softmax over k (warp-wide) ----
    const int klen = klens[b];
    const int kb = lane * 4;                       // base k within group
    float m = -3.0e38f;
    #pragma unroll
    for (int g = 0; g < NG; g++) {
        float* a = (float*)&acc[g];
        #pragma unroll
        for (int j = 0; j < 4; j++)
            if (g * 128 + kb + j < klen) m = fmaxf(m, a[j]);
    }
    #pragma unroll
    for (int o = 16; o > 0; o >>= 1) m = fmaxf(m, __shfl_xor_sync(0xffffffffu, m, o));

    float sum = 0.f;
    #pragma unroll
    for (int g = 0; g < NG; g++) {
        float* a = (float*)&acc[g];
        #pragma unroll
        for (int j = 0; j < 4; j++) {
            const float p = (g * 128 + kb + j < klen) ? __expf(a[j] - m) : 0.f;
            a[j] = p;
            sum += p;
        }
    }
    #pragma unroll
    for (int o = 16; o > 0; o >>= 1) sum += __shfl_xor_sync(0xffffffffu, sum, o);
    const float inv = 1.0f / sum;

    float* pr = probs + w * LK;
    const int attbase = (bh * LQ + q) * LK;
    #pragma unroll
    for (int g = 0; g < NG; g++) {
        float4 p4;
        p4.x = acc[g].x * inv; p4.y = acc[g].y * inv;
        p4.z = acc[g].z * inv; p4.w = acc[g].w * inv;
        ((float4*)(pr + g * 128))[lane] = p4;                      // STS.128
        if (attp) ((float4*)(attp + attbase + g * 128))[lane] = p4; // STG.128
    }
    __syncwarp();

    // ---- AV: lanes switch role to d; 4 independent accumulators ----
    float o0 = 0.f, o1 = 0.f, o2 = 0.f, o3 = 0.f;
    int kk = 0;
    for (; kk + 4 <= klen; kk += 4) {
        o0 = fmaf(pr[kk + 0], vs[(kk + 0) * 32 + lane], o0);
        o1 = fmaf(pr[kk + 1], vs[(kk + 1) * 32 + lane], o1);
        o2 = fmaf(pr[kk + 2], vs[(kk + 2) * 32 + lane], o2);
        o3 = fmaf(pr[kk + 3], vs[(kk + 3) * 32 + lane], o3);
    }
    for (; kk < klen; kk++) o0 = fmaf(pr[kk], vs[kk * 32 + lane], o0);
    const float o = (o0 + o1) + (o2 + o3);

    const int qlen = qlens[b];
    outp[((b * LQ + q) * NH + h) * 32 + lane] = (q < qlen) ? o : 0.f;
}

// ---------------------------------------------------------------------------
extern "C" void kernel_launch(void* const* d_in, const int* in_sizes, int n_in,
                              void* d_out, int out_size)
{
    const float* q    = (const float*)d_in[0];
    const float* k    = (const float*)d_in[1];
    const float* v    = (const float*)d_in[2];
    const int*   qlen = (const int*)  d_in[3];
    const int*   klen = (const int*)  d_in[4];
    const float* w1   = (const float*)d_in[5];
    const float* b1   = (const float*)d_in[6];
    const float* w2   = (const float*)d_in[7];

    float* outp = (float*)d_out;
    const int OUT_ELEMS = BS * LQ * NH * DV;          // 196608
    const int ATT_ELEMS = BH * LQ * LK;               // 2359296
    float* attp = (out_size >= OUT_ELEMS + ATT_ELEMS) ? (outp + OUT_ELEMS) : nullptr;

    pre_kernel<<<dim3(LQ / 32, BH, 2), 256>>>(q, k, w1, b1);

    cudaFuncSetAttribute(main_kernel, cudaFuncAttributeMaxDynamicSharedMemorySize, SMEM_BYTES);
    main_kernel<<<dim3(LQ / QTILE, BH), 512, SMEM_BYTES>>>(v, qlen, klen, w2, outp, attp);
}